// round 2
// baseline (speedup 1.0000x reference)
#include <cuda_runtime.h>

#define Bq   8
#define Nq   2048
#define DIN  128
#define DOUT 64
#define MT   64
#define NT   64

// Scratch (allocation-free rule: device globals)
__device__ float g_xp[Bq * Nq * DOUT];   // projected features [b][n][d]
__device__ float g_es[Bq * Nq];          // e_src per node
__device__ float g_ed[Bq * Nq];          // e_dst per node

// ---------------------------------------------------------------------------
// Kernel A: xp = x @ W^T + b.  One block = 16 rows; W staged in padded SMEM.
// ---------------------------------------------------------------------------
__global__ __launch_bounds__(256) void k_xproj(const float* __restrict__ x,
                                               const float* __restrict__ W,
                                               const float* __restrict__ bvec) {
    __shared__ float Wsh[DOUT * 132];   // pad 128->132 to break bank conflicts
    __shared__ float xsh[16 * DIN];

    int tid = threadIdx.x;
    for (int i = tid; i < DOUT * DIN; i += 256)
        Wsh[(i >> 7) * 132 + (i & 127)] = W[i];
    int row0 = blockIdx.x * 16;
    for (int i = tid; i < 16 * DIN; i += 256)
        xsh[i] = x[(size_t)row0 * DIN + i];
    __syncthreads();

    int g = tid >> 6;      // group 0..3 (64 threads each)
    int d = tid & 63;      // output feature
    float bb = bvec[d];
    #pragma unroll
    for (int rr = 0; rr < 4; rr++) {
        int rl = g * 4 + rr;
        const float* xr = &xsh[rl * DIN];
        float acc = bb;
        #pragma unroll
        for (int k = 0; k < DIN; k += 4) {
            float4 w4 = *(const float4*)&Wsh[d * 132 + k];
            float4 x4 = *(const float4*)&xr[k];
            acc += x4.x * w4.x;
            acc += x4.y * w4.y;
            acc += x4.z * w4.z;
            acc += x4.w * w4.w;
        }
        g_xp[(size_t)(row0 + rl) * DOUT + d] = acc;
    }
}

// ---------------------------------------------------------------------------
// Kernel A2: es[n] = xp[n]·a_src, ed[n] = xp[n]·a_dst.  One warp per row.
// ---------------------------------------------------------------------------
__global__ __launch_bounds__(256) void k_attvec(const float* __restrict__ a) {
    int tid = threadIdx.x;
    int w = tid >> 5, l = tid & 31;
    int row = blockIdx.x * 8 + w;
    float2 v  = *(const float2*)&g_xp[(size_t)row * DOUT + 2 * l];
    float2 as = *(const float2*)&a[2 * l];
    float2 ad = *(const float2*)&a[DOUT + 2 * l];
    float s = v.x * as.x + v.y * as.y;
    float t = v.x * ad.x + v.y * ad.y;
    #pragma unroll
    for (int off = 16; off; off >>= 1) {
        s += __shfl_xor_sync(0xffffffffu, s, off);
        t += __shfl_xor_sync(0xffffffffu, t, off);
    }
    if (l == 0) { g_es[row] = s; g_ed[row] = t; }
}

// Packed dual-fp32 FMA (Blackwell FFMA2)
__device__ __forceinline__ unsigned long long fma2(unsigned long long a,
                                                   unsigned long long b,
                                                   unsigned long long c) {
    unsigned long long d;
    asm("fma.rn.f32x2 %0, %1, %2, %3;" : "=l"(d) : "l"(a), "l"(b), "l"(c));
    return d;
}

// ---------------------------------------------------------------------------
// Kernel B: fused masked-softmax attention + aggregation.
// Block = (batch b, 64 m-rows). 8 warps, each warp owns 8 m-rows, lane owns a
// d-pair. w tile (64m x 64n) built in SMEM pre-packed as (w,w) float2 so the
// inner loop is LDS.128 broadcast + 2 FFMA2 per (m, 2n).
// ---------------------------------------------------------------------------
__global__ __launch_bounds__(256) void k_gat(const int* __restrict__ adj,
                                             float* __restrict__ out) {
    __shared__ float2 wsh[MT][NT];   // 32 KB

    int tid = threadIdx.x;
    int b  = blockIdx.x >> 5;
    int m0 = (blockIdx.x & 31) * MT;
    int g = tid >> 5, l = tid & 31;

    unsigned long long acc[8];
    float wsum[8];
    #pragma unroll
    for (int j = 0; j < 8; j++) { acc[j] = 0ULL; wsum[j] = 0.f; }

    const float* es  = &g_es[b * Nq];
    const float* ed  = &g_ed[b * Nq];
    const float* xpb = &g_xp[(size_t)b * Nq * DOUT];
    const int* adjb  = adj + (size_t)b * Nq * Nq + (size_t)m0 * Nq;

    int nl4  = (tid & 15) << 2;   // n offset within tile (phase 1)
    int mrow = tid >> 4;          // m offset within tile (phase 1)

    for (int n0 = 0; n0 < Nq; n0 += NT) {
        // ---- phase 1: build w tile (masked leaky-relu exp), packed (w,w) ----
        float4 edv = *(const float4*)&ed[n0 + nl4];
        #pragma unroll
        for (int r = 0; r < 4; r++) {
            int m = mrow + (r << 4);
            float esv = es[m0 + m];
            int4 av = *(const int4*)&adjb[(size_t)m * Nq + n0 + nl4];
            float e0 = esv + edv.x, e1 = esv + edv.y;
            float e2 = esv + edv.z, e3 = esv + edv.w;
            e0 = fmaxf(e0, 0.2f * e0);
            e1 = fmaxf(e1, 0.2f * e1);
            e2 = fmaxf(e2, 0.2f * e2);
            e3 = fmaxf(e3, 0.2f * e3);
            float w0 = av.x ? __expf(e0) : 0.f;
            float w1 = av.y ? __expf(e1) : 0.f;
            float w2 = av.z ? __expf(e2) : 0.f;
            float w3 = av.w ? __expf(e3) : 0.f;
            *(float4*)&wsh[m][nl4]     = make_float4(w0, w0, w1, w1);
            *(float4*)&wsh[m][nl4 + 2] = make_float4(w2, w2, w3, w3);
        }
        __syncthreads();

        // ---- phase 2: acc[m] += w[m][n] * xp[n][dpair], 2 n per step ----
        const float2* xrow = (const float2*)&xpb[(size_t)n0 * DOUT];
        #pragma unroll 4
        for (int nn = 0; nn < NT; nn += 2) {
            unsigned long long x0 = *(const unsigned long long*)&xrow[nn * 32 + l];
            unsigned long long x1 = *(const unsigned long long*)&xrow[nn * 32 + 32 + l];
            #pragma unroll
            for (int j = 0; j < 8; j++) {
                ulonglong2 wq = *(const ulonglong2*)&wsh[g * 8 + j][nn];
                acc[j] = fma2(wq.x, x0, acc[j]);
                acc[j] = fma2(wq.y, x1, acc[j]);
            }
        }

        // ---- per-lane partial denominators from the w tile ----
        #pragma unroll
        for (int j = 0; j < 8; j++) {
            float4 wr = *(const float4*)&wsh[g * 8 + j][2 * l];
            wsum[j] += wr.x + wr.z;
        }
        __syncthreads();
    }

    // reduce denominators across the warp
    #pragma unroll
    for (int j = 0; j < 8; j++) {
        float s = wsum[j];
        #pragma unroll
        for (int off = 16; off; off >>= 1)
            s += __shfl_xor_sync(0xffffffffu, s, off);
        wsum[j] = s;
    }

    // normalize + write
    #pragma unroll
    for (int j = 0; j < 8; j++) {
        int m = m0 + g * 8 + j;
        float inv = 1.0f / wsum[j];
        float ax, ay;
        asm("mov.b64 {%0,%1}, %2;" : "=f"(ax), "=f"(ay) : "l"(acc[j]));
        float2 o;
        o.x = ax * inv;
        o.y = ay * inv;
        *(float2*)&out[((size_t)b * Nq + m) * DOUT + 2 * l] = o;
    }
}

// ---------------------------------------------------------------------------
extern "C" void kernel_launch(void* const* d_in, const int* in_sizes, int n_in,
                              void* d_out, int out_size) {
    const float* x    = (const float*)d_in[0];
    const int*   adj  = (const int*)d_in[1];
    const float* W    = (const float*)d_in[2];
    const float* bvec = (const float*)d_in[3];
    const float* a    = (const float*)d_in[4];
    float* out = (float*)d_out;

    k_xproj<<<Bq * Nq / 16, 256>>>(x, W, bvec);
    k_attvec<<<Bq * Nq / 8, 256>>>(a);
    k_gat<<<Bq * (Nq / MT), 256>>>(adj, out);
}

// round 5
// speedup vs baseline: 6.2888x; 6.2888x over previous
#include <cuda_runtime.h>
#include <cstdint>

#define Bq   8
#define Nq   2048
#define DIN  128
#define DOUT 64
#define PIT  132   // smem pitch (floats): 132 mod 32 = 4 -> conflict-free frags

__device__ float g_xpT[Bq * DOUT * Nq];  // projected features, TRANSPOSED [b][d][n]
__device__ float g_es[Bq * Nq];
__device__ float g_ed[Bq * Nq];

static __device__ __forceinline__ float to_tf32(float x) {
    uint32_t r;
    asm("cvt.rna.tf32.f32 %0, %1;" : "=r"(r) : "f"(x));
    return __uint_as_float(r);
}

// D += A(16x8) * B(8x8), tf32 inputs, fp32 accum
static __device__ __forceinline__ void mma8(float* c, const uint32_t* a,
                                            uint32_t b0, uint32_t b1) {
    asm volatile(
        "mma.sync.aligned.m16n8k8.row.col.f32.tf32.tf32.f32 "
        "{%0,%1,%2,%3}, {%4,%5,%6,%7}, {%8,%9}, {%0,%1,%2,%3};"
        : "+f"(c[0]), "+f"(c[1]), "+f"(c[2]), "+f"(c[3])
        : "r"(a[0]), "r"(a[1]), "r"(a[2]), "r"(a[3]), "r"(b0), "r"(b1));
}

// ---------------------------------------------------------------------------
// Kernel 1: xp = x @ W^T + b via mma.sync; epilogue computes es/ed and stores
// xp transposed (tf32-rounded) to g_xpT. One block = 128 rows of x.
// ---------------------------------------------------------------------------
#define PJ_AS   0                       // 128*PIT
#define PJ_WS   (128 * PIT)             // 64*PIT
#define PJ_BS   (PJ_WS + 64 * PIT)      // 64
#define PJ_ASR  (PJ_BS + 64)            // 64
#define PJ_ADR  (PJ_ASR + 64)           // 64
#define PJ_ESH  (PJ_ADR + 64)           // 256
#define PJ_EDH  (PJ_ESH + 256)          // 256
#define PJ_SIZE ((PJ_EDH + 256) * 4)

__global__ void __launch_bounds__(256, 1)
k_proj(const float* __restrict__ x, const float* __restrict__ W,
       const float* __restrict__ bvec, const float* __restrict__ a) {
    extern __shared__ float sh[];
    float* AS  = sh + PJ_AS;
    float* WS  = sh + PJ_WS;
    float* bsh = sh + PJ_BS;
    float* asr = sh + PJ_ASR;
    float* adr = sh + PJ_ADR;
    float* esh = sh + PJ_ESH;
    float* edh = sh + PJ_EDH;

    int tid = threadIdx.x, wid = tid >> 5, lid = tid & 31;
    int g = lid >> 2, tg = lid & 3;
    int row0 = blockIdx.x << 7;

    // x tile -> AS (tf32-rounded). lanes cover consecutive rows: STS conflict-free.
    {
        int r = tid & 127, half = tid >> 7;
        const float4* src = (const float4*)(x + (size_t)(row0 + r) * DIN + half * 64);
        float* dst = AS + r * PIT + half * 64;
        #pragma unroll
        for (int i = 0; i < 16; i++) {
            float4 v = src[i];
            v.x = to_tf32(v.x); v.y = to_tf32(v.y);
            v.z = to_tf32(v.z); v.w = to_tf32(v.w);
            ((float4*)dst)[i] = v;
        }
    }
    // W -> WS (tf32-rounded)
    {
        int d = tid & 63, q = tid >> 6;
        const float4* src = (const float4*)(W + (size_t)d * DIN + q * 32);
        float* dst = WS + d * PIT + q * 32;
        #pragma unroll
        for (int i = 0; i < 8; i++) {
            float4 v = src[i];
            v.x = to_tf32(v.x); v.y = to_tf32(v.y);
            v.z = to_tf32(v.z); v.w = to_tf32(v.w);
            ((float4*)dst)[i] = v;
        }
    }
    if (tid < 64) {
        bsh[tid] = bvec[tid];
        asr[tid] = a[tid];
        adr[tid] = a[DOUT + tid];
    }
    __syncthreads();

    float acc[2][4][4];
    #pragma unroll
    for (int t = 0; t < 2; t++)
        #pragma unroll
        for (int j = 0; j < 4; j++)
            #pragma unroll
            for (int c = 0; c < 4; c++) acc[t][j][c] = 0.f;

    int gm = wid >> 1, h = wid & 1;
    const float* Abase = AS + (32 * gm + g) * PIT + tg;
    const float* Bbase = WS + (32 * h + g) * PIT + tg;

    #pragma unroll
    for (int ks = 0; ks < 16; ks++) {
        int kb = ks * 8;
        uint32_t A[2][4];
        #pragma unroll
        for (int t = 0; t < 2; t++) {
            const float* ap = Abase + t * 16 * PIT + kb;
            A[t][0] = __float_as_uint(ap[0]);
            A[t][1] = __float_as_uint(ap[8 * PIT]);
            A[t][2] = __float_as_uint(ap[4]);
            A[t][3] = __float_as_uint(ap[8 * PIT + 4]);
        }
        #pragma unroll
        for (int j = 0; j < 4; j++) {
            const float* bp = Bbase + j * 8 * PIT + kb;
            uint32_t B0 = __float_as_uint(bp[0]);
            uint32_t B1 = __float_as_uint(bp[4]);
            mma8(acc[0][j], A[0], B0, B1);
            mma8(acc[1][j], A[1], B0, B1);
        }
    }

    // epilogue: bias, es/ed dots, transposed tf32 store
    int b = row0 >> 11, nloc = row0 & (Nq - 1);
    #pragma unroll
    for (int t = 0; t < 2; t++) {
        #pragma unroll
        for (int rw = 0; rw < 2; rw++) {
            int m = 32 * gm + g + 16 * t + 8 * rw;
            float es = 0.f, ed = 0.f;
            #pragma unroll
            for (int j = 0; j < 4; j++) {
                int d = 32 * h + 8 * j + 2 * tg;
                float f0 = acc[t][j][2 * rw]     + bsh[d];
                float f1 = acc[t][j][2 * rw + 1] + bsh[d + 1];
                es += f0 * asr[d] + f1 * asr[d + 1];
                ed += f0 * adr[d] + f1 * adr[d + 1];
                float* p = g_xpT + ((size_t)b * DOUT + d) * Nq + nloc + m;
                p[0]  = to_tf32(f0);
                p[Nq] = to_tf32(f1);
            }
            es += __shfl_xor_sync(0xffffffffu, es, 1);
            es += __shfl_xor_sync(0xffffffffu, es, 2);
            ed += __shfl_xor_sync(0xffffffffu, ed, 1);
            ed += __shfl_xor_sync(0xffffffffu, ed, 2);
            if (tg == 0) { esh[h * 128 + m] = es; edh[h * 128 + m] = ed; }
        }
    }
    __syncthreads();
    if (tid < 128) {
        g_es[row0 + tid] = esh[tid] + esh[128 + tid];
        g_ed[row0 + tid] = edh[tid] + edh[128 + tid];
    }
}

// ---------------------------------------------------------------------------
// Kernel 2: fused masked-softmax attention + aggregation via mma.sync.
// Block = (b, 128 m-rows); 16 n-tiles of 128. P tile built with exp-table
// trick; D[128x64] accumulated in registers; fp32 denominators alongside.
// ---------------------------------------------------------------------------
#define GA_PS   0                        // 128*PIT
#define GA_XT   (128 * PIT)              // 64*PIT
#define GA_E1   (GA_XT + 64 * PIT)       // 2048
#define GA_EA   (GA_E1 + 2048)           // 2048
#define GA_S1   (GA_EA + 2048)           // 128
#define GA_SA   (GA_S1 + 128)            // 128
#define GA_DS   (GA_SA + 128)            // 128
#define GA_SIZE ((GA_DS + 128) * 4)

__global__ void __launch_bounds__(256, 1)
k_gat(const int* __restrict__ adj, float* __restrict__ out) {
    extern __shared__ float sh[];
    float* PS  = sh + GA_PS;
    float* XT  = sh + GA_XT;
    float* E1n = sh + GA_E1;
    float* Ean = sh + GA_EA;
    float* Es1 = sh + GA_S1;
    float* Esa = sh + GA_SA;
    float* dsh = sh + GA_DS;

    int tid = threadIdx.x, wid = tid >> 5, lid = tid & 31;
    int g = lid >> 2, tg = lid & 3;
    int b  = blockIdx.x >> 4;
    int m0 = (blockIdx.x & 15) << 7;

    // exp tables: whole-batch ed, per-block es
    {
        const float* edb = g_ed + b * Nq;
        #pragma unroll
        for (int i = 0; i < 8; i++) {
            int n = tid + 256 * i;
            float v = edb[n];
            E1n[n] = __expf(v);
            Ean[n] = __expf(0.2f * v);
        }
        if (tid < 128) {
            float v = g_es[b * Nq + m0 + tid];
            Es1[tid] = __expf(v);
            Esa[tid] = __expf(0.2f * v);
        }
    }
    __syncthreads();

    float acc[2][4][4];
    #pragma unroll
    for (int t = 0; t < 2; t++)
        #pragma unroll
        for (int j = 0; j < 4; j++)
            #pragma unroll
            for (int c = 0; c < 4; c++) acc[t][j][c] = 0.f;
    float dsum[16];
    #pragma unroll
    for (int i = 0; i < 16; i++) dsum[i] = 0.f;

    const int*   adjb = adj + (size_t)b * Nq * Nq + (size_t)m0 * Nq;
    const float* gxT  = g_xpT + (size_t)b * DOUT * Nq;

    int gm = wid >> 1, h = wid & 1;
    const float* Abase = PS + (32 * gm + g) * PIT + tg;
    const float* Bbase = XT + (32 * h + g) * PIT + tg;
    int dX = tid & 63, cX = tid >> 6;    // XT loader: consecutive d per quarter-warp

    for (int tile = 0; tile < 16; tile++) {
        int n0 = tile << 7;

        // ---- xp^T tile copy (already transposed + tf32-rounded in gmem) ----
        {
            const float4* src = (const float4*)(gxT + (size_t)dX * Nq + n0 + cX * 32);
            float* dst = XT + dX * PIT + cX * 32;
            #pragma unroll
            for (int i = 0; i < 8; i++) ((float4*)dst)[i] = src[i];
        }

        // ---- P tile: warp w owns rows 8*it + w; lanes = 4 consecutive n ----
        #pragma unroll
        for (int it = 0; it < 16; it++) {
            int m = (it << 3) + wid;
            float e1m = Es1[m], eam = Esa[m];
            int4 av = *(const int4*)(adjb + (size_t)m * Nq + n0 + 4 * lid);
            float4 e1 = *(const float4*)(E1n + n0 + 4 * lid);
            float4 ea = *(const float4*)(Ean + n0 + 4 * lid);
            float p0 = av.x ? to_tf32(fmaxf(e1m * e1.x, eam * ea.x)) : 0.f;
            float p1 = av.y ? to_tf32(fmaxf(e1m * e1.y, eam * ea.y)) : 0.f;
            float p2 = av.z ? to_tf32(fmaxf(e1m * e1.z, eam * ea.z)) : 0.f;
            float p3 = av.w ? to_tf32(fmaxf(e1m * e1.w, eam * ea.w)) : 0.f;
            dsum[it] += (p0 + p1) + (p2 + p3);
            *(float4*)(PS + m * PIT + 4 * lid) = make_float4(p0, p1, p2, p3);
        }
        __syncthreads();

        // ---- MMA: D += P(128x128) * xpT(128x64) ----
        #pragma unroll
        for (int ks = 0; ks < 16; ks++) {
            int kb = ks * 8;
            uint32_t A[2][4];
            #pragma unroll
            for (int t = 0; t < 2; t++) {
                const float* ap = Abase + t * 16 * PIT + kb;
                A[t][0] = __float_as_uint(ap[0]);
                A[t][1] = __float_as_uint(ap[8 * PIT]);
                A[t][2] = __float_as_uint(ap[4]);
                A[t][3] = __float_as_uint(ap[8 * PIT + 4]);
            }
            #pragma unroll
            for (int j = 0; j < 4; j++) {
                const float* bp = Bbase + j * 8 * PIT + kb;
                uint32_t B0 = __float_as_uint(bp[0]);
                uint32_t B1 = __float_as_uint(bp[4]);
                mma8(acc[0][j], A[0], B0, B1);
                mma8(acc[1][j], A[1], B0, B1);
            }
        }
        __syncthreads();
    }

    // ---- denominators: reduce 32 lanes per row ----
    #pragma unroll
    for (int it = 0; it < 16; it++) {
        float v = dsum[it];
        v += __shfl_xor_sync(0xffffffffu, v, 16);
        v += __shfl_xor_sync(0xffffffffu, v, 8);
        v += __shfl_xor_sync(0xffffffffu, v, 4);
        v += __shfl_xor_sync(0xffffffffu, v, 2);
        v += __shfl_xor_sync(0xffffffffu, v, 1);
        if (lid == 0) dsh[(it << 3) + wid] = v;
    }
    __syncthreads();

    // ---- normalize + write (full 32B sectors per store) ----
    float* ob = out + ((size_t)b * Nq + m0) * DOUT;
    #pragma unroll
    for (int t = 0; t < 2; t++) {
        #pragma unroll
        for (int rw = 0; rw < 2; rw++) {
            int m = 32 * gm + g + 16 * t + 8 * rw;
            float inv = 1.0f / dsh[m];
            #pragma unroll
            for (int j = 0; j < 4; j++) {
                float2 o = make_float2(acc[t][j][2 * rw] * inv,
                                       acc[t][j][2 * rw + 1] * inv);
                *(float2*)(ob + (size_t)m * DOUT + 32 * h + 8 * j + 2 * tg) = o;
            }
        }
    }
}

// ---------------------------------------------------------------------------
extern "C" void kernel_launch(void* const* d_in, const int* in_sizes, int n_in,
                              void* d_out, int out_size) {
    const float* x    = (const float*)d_in[0];
    const int*   adj  = (const int*)d_in[1];
    const float* W    = (const float*)d_in[2];
    const float* bvec = (const float*)d_in[3];
    const float* a    = (const float*)d_in[4];
    float* out = (float*)d_out;

    cudaFuncSetAttribute(k_proj, cudaFuncAttributeMaxDynamicSharedMemorySize, PJ_SIZE);
    cudaFuncSetAttribute(k_gat,  cudaFuncAttributeMaxDynamicSharedMemorySize, GA_SIZE);

    k_proj<<<Bq * Nq / 128, 256, PJ_SIZE>>>(x, W, bvec, a);
    k_gat<<<Bq * (Nq / 128), 256, GA_SIZE>>>(adj, out);
}